// round 8
// baseline (speedup 1.0000x reference)
#include <cuda_runtime.h>
#include <cuda_bf16.h>

#define MAXN 100000
#define MAXE 1700000
#define FDIM 64
#define NB_MAX ((MAXN + 255) / 256)   // 391

// Scratch — __device__ globals, referenced DIRECTLY in kernels.
__device__ int   g_is64;            // 1 if edge_index is int64, 0 if int32
__device__ int   g_cnt[MAXN];
__device__ int   g_off[MAXN + 1];
__device__ int   g_cursor[MAXN];
__device__ int   g_srcs[MAXE];
__device__ int   g_blockoff[NB_MAX];
__device__ float g_dinv[MAXN];
__device__ float g_H1[(size_t)MAXN * FDIM];    // raw hidden, layer 1
__device__ float g_agg1[(size_t)MAXN * FDIM];
__device__ float g_H2[(size_t)MAXN * FDIM];    // raw hidden, layer 2

// ---------------------------------------------------------------------------
// init: detect edge dtype (thread 0) + zero g_cnt.
// ---------------------------------------------------------------------------
__global__ void init_kernel(const unsigned int* __restrict__ raw, int M, int E) {
    int i = blockIdx.x * blockDim.x + threadIdx.x;
    if (i < M) g_cnt[i] = 0;
    if (i == 0) {
        int nz = 0;
        int lim = E < 64 ? E : 64;
        for (int k = 0; k < lim; k++)
            if (raw[2 * k + 1] != 0u) nz++;
        g_is64 = (nz == 0) ? 1 : 0;
    }
}

__device__ __forceinline__ int edge_at(const void* ei, int is64, size_t idx) {
    if (is64) return (int)((const long long*)ei)[idx];
    return ((const int*)ei)[idx];
}

__global__ void count_kernel(const void* __restrict__ ei, int E) {
    int e = blockIdx.x * blockDim.x + threadIdx.x;
    if (e < E) {
        int is64 = g_is64;
        int c = edge_at(ei, is64, (size_t)E + e);  // target node
        atomicAdd(&g_cnt[c], 1);
    }
}

// --- 3-phase grid-wide exclusive scan of g_cnt -> g_off (A also emits dinv) ---
__global__ void scan_a_kernel(int M) {
    __shared__ int sh[256];
    int tid = threadIdx.x;
    int i = blockIdx.x * 256 + tid;
    int v = (i < M) ? g_cnt[i] : 0;
    if (i < M) g_dinv[i] = rsqrtf((float)(v + 1));
    sh[tid] = v;
    __syncthreads();
#pragma unroll
    for (int d = 128; d > 0; d >>= 1) {
        if (tid < d) sh[tid] += sh[tid + d];
        __syncthreads();
    }
    if (tid == 0) g_blockoff[blockIdx.x] = sh[0];
}

__global__ void scan_b_kernel(int NB, int M) {
    __shared__ int sh[1024];
    int tid = threadIdx.x;
    int v = (tid < NB) ? g_blockoff[tid] : 0;
    sh[tid] = v;
    __syncthreads();
    for (int d = 1; d < 1024; d <<= 1) {
        int t = (tid >= d) ? sh[tid - d] : 0;
        __syncthreads();
        sh[tid] += t;
        __syncthreads();
    }
    if (tid < NB) g_blockoff[tid] = sh[tid] - v;   // exclusive
    if (tid == NB - 1) g_off[M] = sh[tid];
}

__global__ void scan_c_kernel(int M) {
    __shared__ int sh[256];
    int tid = threadIdx.x;
    int i = blockIdx.x * 256 + tid;
    int v = (i < M) ? g_cnt[i] : 0;
    sh[tid] = v;
    __syncthreads();
    for (int d = 1; d < 256; d <<= 1) {
        int t = (tid >= d) ? sh[tid - d] : 0;
        __syncthreads();
        sh[tid] += t;
        __syncthreads();
    }
    if (i < M) {
        int pos = g_blockoff[blockIdx.x] + sh[tid] - v;  // exclusive
        g_off[i] = pos;
        g_cursor[i] = pos;
    }
}

__global__ void fill_kernel(const void* __restrict__ ei, int E) {
    int e = blockIdx.x * blockDim.x + threadIdx.x;
    if (e < E) {
        int is64 = g_is64;
        int r = edge_at(ei, is64, (size_t)e);           // source
        int c = edge_at(ei, is64, (size_t)E + e);       // target
        int pos = atomicAdd(&g_cursor[c], 1);
        g_srcs[pos] = r;
    }
}

// ---------------------------------------------------------------------------
// GEMM: H = act(X) @ W (RAW — no dinv; dinv applied in gather).
// 256 threads -> 128x64 tile; thread = 8x4; k-major transposed X tile.
// (R6's proven shape: fma 40%, ~52us for K=128, minus the AGG write.)
// ---------------------------------------------------------------------------
template <int K, bool LAYER2>
__global__ void gcn_gemm_kernel(const float* __restrict__ Xin,
                                const float* __restrict__ W, int M) {
    const float* X = LAYER2 ? g_agg1 : Xin;
    float*       H = LAYER2 ? g_H2   : g_H1;

    constexpr int KT = 32;
    constexpr int XS = 132;
    __shared__ float Ws[KT][64];         // 8 KB
    __shared__ float xsT[KT][XS];        // 16.9 KB, k-major

    const int tid = threadIdx.x;
    const int tx = tid & 15;             // cols tx*4..+3
    const int ty = tid >> 4;             // rows ty*8..+7
    const int row0 = blockIdx.x * 128;

    float acc[8][4];
#pragma unroll
    for (int r = 0; r < 8; r++)
#pragma unroll
        for (int c = 0; c < 4; c++) acc[r][c] = 0.0f;

    for (int k0 = 0; k0 < K; k0 += KT) {
#pragma unroll
        for (int i = tid; i < KT * 16; i += 256) {
            int kk = i >> 4, cc = (i & 15) * 4;
            *(float4*)&Ws[kk][cc] = *(const float4*)&W[(size_t)(k0 + kk) * 64 + cc];
        }
#pragma unroll
        for (int i = tid; i < 128 * 8; i += 256) {
            int r = i >> 3;
            int j = i & 7;
            int row = row0 + r;
            float4 v = make_float4(0.f, 0.f, 0.f, 0.f);
            if (row < M)
                v = *(const float4*)&X[(size_t)row * K + k0 + j * 4];
            if (LAYER2) {
                v.x = fmaxf(v.x, 0.f); v.y = fmaxf(v.y, 0.f);
                v.z = fmaxf(v.z, 0.f); v.w = fmaxf(v.w, 0.f);
            }
            xsT[j * 4 + 0][r] = v.x;
            xsT[j * 4 + 1][r] = v.y;
            xsT[j * 4 + 2][r] = v.z;
            xsT[j * 4 + 3][r] = v.w;
        }
        __syncthreads();

#pragma unroll 4
        for (int k = 0; k < KT; k++) {
            float4 w  = *(const float4*)&Ws[k][tx * 4];
            float4 xa = *(const float4*)&xsT[k][ty * 8];
            float4 xb = *(const float4*)&xsT[k][ty * 8 + 4];
            const float xv[8] = {xa.x, xa.y, xa.z, xa.w, xb.x, xb.y, xb.z, xb.w};
#pragma unroll
            for (int r = 0; r < 8; r++) {
                acc[r][0] += xv[r] * w.x;
                acc[r][1] += xv[r] * w.y;
                acc[r][2] += xv[r] * w.z;
                acc[r][3] += xv[r] * w.w;
            }
        }
        __syncthreads();
    }

#pragma unroll
    for (int r = 0; r < 8; r++) {
        int row = row0 + ty * 8 + r;
        if (row < M) {
            *(float4*)&H[(size_t)row * 64 + tx * 4] =
                make_float4(acc[r][0], acc[r][1], acc[r][2], acc[r][3]);
        }
    }
}

// ---------------------------------------------------------------------------
// CSR gather (dinv applied here):
//   agg[n] = bias + dinv[n] * ( dinv[n]*H[n] + sum_src dinv[src]*H[src] )
// 16 threads per node, one float4 channel slice each. No atomics.
// ---------------------------------------------------------------------------
template <bool LAYER2>
__global__ void gather_kernel(const float* __restrict__ bias,
                              float* __restrict__ AGGout, int M) {
    const float* H   = LAYER2 ? g_H2   : g_H1;
    float*       agg = LAYER2 ? AGGout : g_agg1;

    long long gid = (long long)blockIdx.x * blockDim.x + threadIdx.x;
    int n = (int)(gid >> 4);
    if (n >= M) return;
    int lane = (int)(gid & 15);

    float dn = g_dinv[n];
    size_t base = (size_t)n * 64 + lane * 4;
    float4 hs = *(const float4*)&H[base];   // self term: dinv[n]*H[n]
    float4 a = make_float4(dn * hs.x, dn * hs.y, dn * hs.z, dn * hs.w);

    int s = g_off[n], e = g_off[n + 1];
#pragma unroll 4
    for (int j = s; j < e; j++) {
        int r = g_srcs[j];
        float w = g_dinv[r];
        float4 h = *(const float4*)&H[(size_t)r * 64 + lane * 4];
        a.x += w * h.x; a.y += w * h.y; a.z += w * h.z; a.w += w * h.w;
    }
    float4 bv = *(const float4*)&bias[lane * 4];
    float4 o = make_float4(bv.x + dn * a.x, bv.y + dn * a.y,
                           bv.z + dn * a.z, bv.w + dn * a.w);
    *(float4*)&agg[base] = o;
}

// ---------------------------------------------------------------------------
// Launch: fork chain B (edge/CSR pipeline) onto a side stream so it overlaps
// with gemm1 on the capture stream; join before gather1. Streams/events are
// created per call and intentionally not destroyed (kernel_launch runs only
// a handful of times; graph replays don't re-enter this function).
// ---------------------------------------------------------------------------
extern "C" void kernel_launch(void* const* d_in, const int* in_sizes, int n_in,
                              void* d_out, int out_size) {
    const float* x  = (const float*)d_in[0];
    const void*  ei = d_in[1];
    const float* W1 = (const float*)d_in[2];
    const float* b1 = (const float*)d_in[3];
    const float* W2 = (const float*)d_in[4];
    const float* b2 = (const float*)d_in[5];
    float*       out = (float*)d_out;

    const int M = in_sizes[0] / 128;   // 100000
    const int E = in_sizes[1] / 2;     // 1600000
    const int NB = (M + 255) / 256;
    const int T = 256;

    cudaStream_t s2;
    cudaStreamCreateWithFlags(&s2, cudaStreamNonBlocking);
    cudaEvent_t e0, eB;
    cudaEventCreateWithFlags(&e0, cudaEventDisableTiming);
    cudaEventCreateWithFlags(&eB, cudaEventDisableTiming);

    // Fork: side stream waits on the head of the capture stream.
    cudaEventRecord(e0, 0);
    cudaStreamWaitEvent(s2, e0, 0);

    // ---- Chain B (s2): edge pipeline -> CSR + dinv ----
    init_kernel<<<(M + T - 1) / T, T, 0, s2>>>((const unsigned int*)ei, M, E);
    count_kernel<<<(E + T - 1) / T, T, 0, s2>>>(ei, E);
    scan_a_kernel<<<NB, 256, 0, s2>>>(M);
    scan_b_kernel<<<1, 1024, 0, s2>>>(NB, M);
    scan_c_kernel<<<NB, 256, 0, s2>>>(M);
    fill_kernel<<<(E + T - 1) / T, T, 0, s2>>>(ei, E);
    cudaEventRecord(eB, s2);

    // ---- Chain A (capture stream): layer-1 GEMM (needs only x, W1) ----
    gcn_gemm_kernel<128, false><<<(M + 127) / 128, T>>>(x, W1, M);

    // ---- Join, then the dependent tail ----
    cudaStreamWaitEvent(0, eB, 0);
    gather_kernel<false><<<(int)(((long long)M * 16 + T - 1) / T), T>>>(b1, nullptr, M);
    gcn_gemm_kernel<64, true><<<(M + 127) / 128, T>>>(nullptr, W2, M);
    gather_kernel<true><<<(int)(((long long)M * 16 + T - 1) / T), T>>>(b2, out, M);
}

// round 10
// speedup vs baseline: 1.0840x; 1.0840x over previous
#include <cuda_runtime.h>
#include <cuda_fp16.h>

#define MAXN 100000
#define MAXE 1700000
#define FDIM 64
#define NB_MAX ((MAXN + 255) / 256)   // 391

// Scratch — __device__ globals, referenced DIRECTLY in kernels.
__device__ int    g_is64;           // 1 if edge_index is int64, 0 if int32
__device__ int    g_cnt[MAXN];
__device__ int    g_off[MAXN + 1];
__device__ int    g_cursor[MAXN];
__device__ int    g_srcs[MAXE];
__device__ int    g_blockoff[NB_MAX];
__device__ float  g_dinv[MAXN];
__device__ __half g_H1h[(size_t)MAXN * FDIM];  // fp16 hidden, layer 1
__device__ float  g_agg1[(size_t)MAXN * FDIM]; // fp32 layer-1 aggregate
__device__ __half g_H2h[(size_t)MAXN * FDIM];  // fp16 hidden, layer 2

// ---------------------------------------------------------------------------
// init: detect edge dtype (thread 0) + zero g_cnt.
// ---------------------------------------------------------------------------
__global__ void init_kernel(const unsigned int* __restrict__ raw, int M, int E) {
    int i = blockIdx.x * blockDim.x + threadIdx.x;
    if (i < M) g_cnt[i] = 0;
    if (i == 0) {
        int nz = 0;
        int lim = E < 64 ? E : 64;
        for (int k = 0; k < lim; k++)
            if (raw[2 * k + 1] != 0u) nz++;
        g_is64 = (nz == 0) ? 1 : 0;
    }
}

__device__ __forceinline__ int edge_at(const void* ei, int is64, size_t idx) {
    if (is64) return (int)((const long long*)ei)[idx];
    return ((const int*)ei)[idx];
}

__global__ void count_kernel(const void* __restrict__ ei, int E) {
    int e = blockIdx.x * blockDim.x + threadIdx.x;
    if (e < E) {
        int is64 = g_is64;
        int c = edge_at(ei, is64, (size_t)E + e);  // target node
        atomicAdd(&g_cnt[c], 1);
    }
}

// --- 3-phase grid-wide exclusive scan of g_cnt -> g_off (A also emits dinv) ---
__global__ void scan_a_kernel(int M) {
    __shared__ int sh[256];
    int tid = threadIdx.x;
    int i = blockIdx.x * 256 + tid;
    int v = (i < M) ? g_cnt[i] : 0;
    if (i < M) g_dinv[i] = rsqrtf((float)(v + 1));
    sh[tid] = v;
    __syncthreads();
#pragma unroll
    for (int d = 128; d > 0; d >>= 1) {
        if (tid < d) sh[tid] += sh[tid + d];
        __syncthreads();
    }
    if (tid == 0) g_blockoff[blockIdx.x] = sh[0];
}

__global__ void scan_b_kernel(int NB, int M) {
    __shared__ int sh[1024];
    int tid = threadIdx.x;
    int v = (tid < NB) ? g_blockoff[tid] : 0;
    sh[tid] = v;
    __syncthreads();
    for (int d = 1; d < 1024; d <<= 1) {
        int t = (tid >= d) ? sh[tid - d] : 0;
        __syncthreads();
        sh[tid] += t;
        __syncthreads();
    }
    if (tid < NB) g_blockoff[tid] = sh[tid] - v;   // exclusive
    if (tid == NB - 1) g_off[M] = sh[tid];
}

__global__ void scan_c_kernel(int M) {
    __shared__ int sh[256];
    int tid = threadIdx.x;
    int i = blockIdx.x * 256 + tid;
    int v = (i < M) ? g_cnt[i] : 0;
    sh[tid] = v;
    __syncthreads();
    for (int d = 1; d < 256; d <<= 1) {
        int t = (tid >= d) ? sh[tid - d] : 0;
        __syncthreads();
        sh[tid] += t;
        __syncthreads();
    }
    if (i < M) {
        int pos = g_blockoff[blockIdx.x] + sh[tid] - v;  // exclusive
        g_off[i] = pos;
        g_cursor[i] = pos;
    }
}

__global__ void fill_kernel(const void* __restrict__ ei, int E) {
    int e = blockIdx.x * blockDim.x + threadIdx.x;
    if (e < E) {
        int is64 = g_is64;
        int r = edge_at(ei, is64, (size_t)e);           // source
        int c = edge_at(ei, is64, (size_t)E + e);       // target
        int pos = atomicAdd(&g_cursor[c], 1);
        g_srcs[pos] = r;
    }
}

// ---------------------------------------------------------------------------
// GEMM: H = act(X) @ W, stored fp16 (dinv applied in gather).
// 256 threads -> 128x64 tile; thread = 8x4; k-major transposed X tile.
// ---------------------------------------------------------------------------
template <int K, bool LAYER2>
__global__ void gcn_gemm_kernel(const float* __restrict__ Xin,
                                const float* __restrict__ W, int M) {
    const float* X = LAYER2 ? g_agg1 : Xin;
    __half*      H = LAYER2 ? g_H2h  : g_H1h;

    constexpr int KT = 32;
    constexpr int XS = 132;
    __shared__ float Ws[KT][64];         // 8 KB
    __shared__ float xsT[KT][XS];        // 16.9 KB, k-major

    const int tid = threadIdx.x;
    const int tx = tid & 15;             // cols tx*4..+3
    const int ty = tid >> 4;             // rows ty*8..+7
    const int row0 = blockIdx.x * 128;

    float acc[8][4];
#pragma unroll
    for (int r = 0; r < 8; r++)
#pragma unroll
        for (int c = 0; c < 4; c++) acc[r][c] = 0.0f;

    for (int k0 = 0; k0 < K; k0 += KT) {
#pragma unroll
        for (int i = tid; i < KT * 16; i += 256) {
            int kk = i >> 4, cc = (i & 15) * 4;
            *(float4*)&Ws[kk][cc] = *(const float4*)&W[(size_t)(k0 + kk) * 64 + cc];
        }
#pragma unroll
        for (int i = tid; i < 128 * 8; i += 256) {
            int r = i >> 3;
            int j = i & 7;
            int row = row0 + r;
            float4 v = make_float4(0.f, 0.f, 0.f, 0.f);
            if (row < M)
                v = *(const float4*)&X[(size_t)row * K + k0 + j * 4];
            if (LAYER2) {
                v.x = fmaxf(v.x, 0.f); v.y = fmaxf(v.y, 0.f);
                v.z = fmaxf(v.z, 0.f); v.w = fmaxf(v.w, 0.f);
            }
            xsT[j * 4 + 0][r] = v.x;
            xsT[j * 4 + 1][r] = v.y;
            xsT[j * 4 + 2][r] = v.z;
            xsT[j * 4 + 3][r] = v.w;
        }
        __syncthreads();

#pragma unroll 4
        for (int k = 0; k < KT; k++) {
            float4 w  = *(const float4*)&Ws[k][tx * 4];
            float4 xa = *(const float4*)&xsT[k][ty * 8];
            float4 xb = *(const float4*)&xsT[k][ty * 8 + 4];
            const float xv[8] = {xa.x, xa.y, xa.z, xa.w, xb.x, xb.y, xb.z, xb.w};
#pragma unroll
            for (int r = 0; r < 8; r++) {
                acc[r][0] += xv[r] * w.x;
                acc[r][1] += xv[r] * w.y;
                acc[r][2] += xv[r] * w.z;
                acc[r][3] += xv[r] * w.w;
            }
        }
        __syncthreads();
    }

#pragma unroll
    for (int r = 0; r < 8; r++) {
        int row = row0 + ty * 8 + r;
        if (row < M) {
            __half2 p0 = __floats2half2_rn(acc[r][0], acc[r][1]);
            __half2 p1 = __floats2half2_rn(acc[r][2], acc[r][3]);
            uint2 st;
            st.x = *(unsigned int*)&p0;
            st.y = *(unsigned int*)&p1;
            // offset row*64 + tx*4 halves = row*128 + tx*8 bytes (8B aligned)
            *(uint2*)&H[(size_t)row * 64 + tx * 4] = st;
        }
    }
}

// ---------------------------------------------------------------------------
// CSR gather (fp16 H, fp32 accumulate):
//   agg[n] = bias + dinv[n]*( dinv[n]*H[n] + sum_src dinv[src]*H[src] )
// 8 threads per node, each owns 8 channels (one uint4 = 8 halves = 16 B).
// Per edge per lane: 1 broadcast idx load + 1 LDG.128. 128 B/edge total.
// ---------------------------------------------------------------------------
template <bool LAYER2>
__global__ void gather_kernel(const float* __restrict__ bias,
                              float* __restrict__ AGGout, int M) {
    const __half* H   = LAYER2 ? g_H2h  : g_H1h;
    float*        agg = LAYER2 ? AGGout : g_agg1;
    const uint4*  Hv  = (const uint4*)H;   // 8 uint4 per node row

    long long gid = (long long)blockIdx.x * blockDim.x + threadIdx.x;
    int n = (int)(gid >> 3);
    if (n >= M) return;
    int lane = (int)(gid & 7);

    float dn = g_dinv[n];
    float a[8];
    {
        uint4 hv = Hv[(size_t)n * 8 + lane];     // self term
        const __half2* h2 = (const __half2*)&hv;
#pragma unroll
        for (int q = 0; q < 4; q++) {
            float2 f = __half22float2(h2[q]);
            a[2 * q + 0] = dn * f.x;
            a[2 * q + 1] = dn * f.y;
        }
    }

    int s = g_off[n], e = g_off[n + 1];
    for (int j = s; j < e; j++) {
        int r = g_srcs[j];                        // broadcast across 8 lanes
        float w = g_dinv[r];
        uint4 hv = Hv[(size_t)r * 8 + lane];
        const __half2* h2 = (const __half2*)&hv;
#pragma unroll
        for (int q = 0; q < 4; q++) {
            float2 f = __half22float2(h2[q]);
            a[2 * q + 0] += w * f.x;
            a[2 * q + 1] += w * f.y;
        }
    }

    size_t base = (size_t)n * 64 + lane * 8;
    float4 b0 = *(const float4*)&bias[lane * 8];
    float4 b1 = *(const float4*)&bias[lane * 8 + 4];
    float4 o0 = make_float4(b0.x + dn * a[0], b0.y + dn * a[1],
                            b0.z + dn * a[2], b0.w + dn * a[3]);
    float4 o1 = make_float4(b1.x + dn * a[4], b1.y + dn * a[5],
                            b1.z + dn * a[6], b1.w + dn * a[7]);
    *(float4*)&agg[base] = o0;
    *(float4*)&agg[base + 4] = o1;
}

// ---------------------------------------------------------------------------
extern "C" void kernel_launch(void* const* d_in, const int* in_sizes, int n_in,
                              void* d_out, int out_size) {
    const float* x  = (const float*)d_in[0];
    const void*  ei = d_in[1];
    const float* W1 = (const float*)d_in[2];
    const float* b1 = (const float*)d_in[3];
    const float* W2 = (const float*)d_in[4];
    const float* b2 = (const float*)d_in[5];
    float*       out = (float*)d_out;

    const int M = in_sizes[0] / 128;   // 100000
    const int E = in_sizes[1] / 2;     // 1600000
    const int NB = (M + 255) / 256;
    const int T = 256;

    // 1-3: dtype detect + counts + dinv/scanA
    init_kernel<<<(M + T - 1) / T, T>>>((const unsigned int*)ei, M, E);
    count_kernel<<<(E + T - 1) / T, T>>>(ei, E);
    scan_a_kernel<<<NB, 256>>>(M);
    // 4: layer-1 GEMM — ncu capture slot
    gcn_gemm_kernel<128, false><<<(M + 127) / 128, T>>>(x, W1, M);
    // 5-7: CSR offsets + fill
    scan_b_kernel<<<1, 1024>>>(NB, M);
    scan_c_kernel<<<NB, 256>>>(M);
    fill_kernel<<<(E + T - 1) / T, T>>>(ei, E);
    // 8: layer-1 aggregate (fp32 out)
    gather_kernel<false><<<(int)(((long long)M * 8 + T - 1) / T), T>>>(b1, nullptr, M);
    // 9-10: layer 2 (gather writes d_out)
    gcn_gemm_kernel<64, true><<<(M + 127) / 128, T>>>(nullptr, W2, M);
    gather_kernel<true><<<(int)(((long long)M * 8 + T - 1) / T), T>>>(b2, out, M);
}

// round 13
// speedup vs baseline: 1.4730x; 1.3589x over previous
#include <cuda_runtime.h>
#include <cuda_fp16.h>
#include <cstdint>

#define MAXN 100000
#define MAXE 1700000
#define FDIM 64
#define NB_MAX ((MAXN + 255) / 256)   // 391

// Scratch — __device__ globals, referenced DIRECTLY in kernels.
__device__ int    g_is64;           // 1 if edge_index is int64, 0 if int32
__device__ int    g_cnt[MAXN];
__device__ int    g_off[MAXN + 1];
__device__ int    g_cursor[MAXN];
__device__ int    g_srcs[MAXE];
__device__ int    g_blockoff[NB_MAX];
__device__ float  g_dinv[MAXN];
__device__ __half g_H1h[(size_t)MAXN * FDIM];  // fp16 hidden, layer 1
__device__ float  g_agg1[(size_t)MAXN * FDIM]; // fp32 layer-1 aggregate
__device__ __half g_H2h[(size_t)MAXN * FDIM];  // fp16 hidden, layer 2

// ---------------------------------------------------------------------------
// init: detect edge dtype (thread 0) + zero g_cnt.
// ---------------------------------------------------------------------------
__global__ void init_kernel(const unsigned int* __restrict__ raw, int M, int E) {
    int i = blockIdx.x * blockDim.x + threadIdx.x;
    if (i < M) g_cnt[i] = 0;
    if (i == 0) {
        int nz = 0;
        int lim = E < 64 ? E : 64;
        for (int k = 0; k < lim; k++)
            if (raw[2 * k + 1] != 0u) nz++;
        g_is64 = (nz == 0) ? 1 : 0;
    }
}

__device__ __forceinline__ int edge_at(const void* ei, int is64, size_t idx) {
    if (is64) return (int)((const long long*)ei)[idx];
    return ((const int*)ei)[idx];
}

__global__ void count_kernel(const void* __restrict__ ei, int E) {
    int e = blockIdx.x * blockDim.x + threadIdx.x;
    if (e < E) {
        int is64 = g_is64;
        int c = edge_at(ei, is64, (size_t)E + e);  // target node
        atomicAdd(&g_cnt[c], 1);
    }
}

// --- 3-phase grid-wide exclusive scan of g_cnt -> g_off (A also emits dinv) ---
__global__ void scan_a_kernel(int M) {
    __shared__ int sh[256];
    int tid = threadIdx.x;
    int i = blockIdx.x * 256 + tid;
    int v = (i < M) ? g_cnt[i] : 0;
    if (i < M) g_dinv[i] = rsqrtf((float)(v + 1));
    sh[tid] = v;
    __syncthreads();
#pragma unroll
    for (int d = 128; d > 0; d >>= 1) {
        if (tid < d) sh[tid] += sh[tid + d];
        __syncthreads();
    }
    if (tid == 0) g_blockoff[blockIdx.x] = sh[0];
}

__global__ void scan_b_kernel(int NB, int M) {
    __shared__ int sh[1024];
    int tid = threadIdx.x;
    int v = (tid < NB) ? g_blockoff[tid] : 0;
    sh[tid] = v;
    __syncthreads();
    for (int d = 1; d < 1024; d <<= 1) {
        int t = (tid >= d) ? sh[tid - d] : 0;
        __syncthreads();
        sh[tid] += t;
        __syncthreads();
    }
    if (tid < NB) g_blockoff[tid] = sh[tid] - v;   // exclusive
    if (tid == NB - 1) g_off[M] = sh[tid];
}

__global__ void scan_c_kernel(int M) {
    __shared__ int sh[256];
    int tid = threadIdx.x;
    int i = blockIdx.x * 256 + tid;
    int v = (i < M) ? g_cnt[i] : 0;
    sh[tid] = v;
    __syncthreads();
    for (int d = 1; d < 256; d <<= 1) {
        int t = (tid >= d) ? sh[tid - d] : 0;
        __syncthreads();
        sh[tid] += t;
        __syncthreads();
    }
    if (i < M) {
        int pos = g_blockoff[blockIdx.x] + sh[tid] - v;  // exclusive
        g_off[i] = pos;
        g_cursor[i] = pos;
    }
}

__global__ void fill_kernel(const void* __restrict__ ei, int E) {
    int e = blockIdx.x * blockDim.x + threadIdx.x;
    if (e < E) {
        int is64 = g_is64;
        int r = edge_at(ei, is64, (size_t)e);           // source
        int c = edge_at(ei, is64, (size_t)E + e);       // target
        int pos = atomicAdd(&g_cursor[c], 1);
        g_srcs[pos] = r;
    }
}

// ---------------------------------------------------------------------------
// Tensor-core GEMM (HMMA): H = fp16( act(X) @ W ), dinv applied in gather.
// 256 threads = 8 warps; CTA tile 128x64; warp tile 16x64.
// mma.sync.m16n8k16 f16xf16->f32; A/B staged fp32->fp16 in smem.
// ---------------------------------------------------------------------------
__device__ __forceinline__ void ldsm_x4(unsigned* r, uint32_t addr) {
    asm volatile("ldmatrix.sync.aligned.m8n8.x4.shared.b16 {%0,%1,%2,%3}, [%4];"
                 : "=r"(r[0]), "=r"(r[1]), "=r"(r[2]), "=r"(r[3]) : "r"(addr));
}
__device__ __forceinline__ void ldsm_x2_trans(unsigned* r, uint32_t addr) {
    asm volatile("ldmatrix.sync.aligned.m8n8.x2.trans.shared.b16 {%0,%1}, [%2];"
                 : "=r"(r[0]), "=r"(r[1]) : "r"(addr));
}
__device__ __forceinline__ void mma16816(float* d, const unsigned* a,
                                         const unsigned* b) {
    asm volatile(
        "mma.sync.aligned.m16n8k16.row.col.f32.f16.f16.f32 "
        "{%0,%1,%2,%3}, {%4,%5,%6,%7}, {%8,%9}, {%0,%1,%2,%3};"
        : "+f"(d[0]), "+f"(d[1]), "+f"(d[2]), "+f"(d[3])
        : "r"(a[0]), "r"(a[1]), "r"(a[2]), "r"(a[3]), "r"(b[0]), "r"(b[1]));
}

template <int K, bool LAYER2>
__global__ void __launch_bounds__(256)
gcn_gemm_kernel(const float* __restrict__ Xin, const float* __restrict__ W,
                int M) {
    const float* X    = LAYER2 ? g_agg1 : Xin;
    __half*      Hout = LAYER2 ? g_H2h  : g_H1h;

    constexpr int KT = 64;
    constexpr int SA = 72;               // A smem stride (halves); 144B rows
    constexpr int SB = 72;               // B smem stride (halves)
    __shared__ __half As[128 * SA];      // 18.4 KB
    __shared__ __half Bs[KT * SB];       // 9.2 KB

    const int tid  = threadIdx.x;
    const int warp = tid >> 5;
    const int lane = tid & 31;
    const int row0 = blockIdx.x * 128;
    const int wm0  = warp * 16;          // warp's row offset in tile

    float acc[8][4];
#pragma unroll
    for (int nf = 0; nf < 8; nf++)
#pragma unroll
        for (int q = 0; q < 4; q++) acc[nf][q] = 0.0f;

    const uint32_t a_base = (uint32_t)__cvta_generic_to_shared(&As[0]);
    const uint32_t b_base = (uint32_t)__cvta_generic_to_shared(&Bs[0]);

    for (int k0 = 0; k0 < K; k0 += KT) {
        // Stage A: 128 rows x 64 k, fp32->fp16 (ReLU for layer 2)
#pragma unroll
        for (int t = 0; t < 8; t++) {
            int idx = tid + t * 256;     // 0..2047
            int r = idx >> 4;            // row in tile
            int j = idx & 15;            // float4 group in k
            int row = row0 + r;
            float4 v = make_float4(0.f, 0.f, 0.f, 0.f);
            if (row < M)
                v = *(const float4*)&X[(size_t)row * K + k0 + j * 4];
            if (LAYER2) {
                v.x = fmaxf(v.x, 0.f); v.y = fmaxf(v.y, 0.f);
                v.z = fmaxf(v.z, 0.f); v.w = fmaxf(v.w, 0.f);
            }
            __half2 h0 = __floats2half2_rn(v.x, v.y);
            __half2 h1 = __floats2half2_rn(v.z, v.w);
            uint2 st;
            st.x = *(unsigned*)&h0;
            st.y = *(unsigned*)&h1;
            *(uint2*)&As[r * SA + j * 4] = st;
        }
        // Stage B: 64 k-rows x 64 n, fp32->fp16, k-major
#pragma unroll
        for (int t = 0; t < 4; t++) {
            int idx = tid + t * 256;     // 0..1023
            int r = idx >> 4;            // k row
            int j = idx & 15;
            float4 v = *(const float4*)&W[(size_t)(k0 + r) * 64 + j * 4];
            __half2 h0 = __floats2half2_rn(v.x, v.y);
            __half2 h1 = __floats2half2_rn(v.z, v.w);
            uint2 st;
            st.x = *(unsigned*)&h0;
            st.y = *(unsigned*)&h1;
            *(uint2*)&Bs[r * SB + j * 4] = st;
        }
        __syncthreads();

#pragma unroll
        for (int ks = 0; ks < KT / 16; ks++) {
            unsigned a[4];
            // A frag: rows wm0+(lane&15), k cols ks*16 + (lane>>4)*8 halves
            uint32_t a_addr = a_base +
                (((wm0 + (lane & 15)) * SA + ks * 16 + (lane >> 4) * 8) << 1);
            ldsm_x4(a, a_addr);
#pragma unroll
            for (int nf = 0; nf < 8; nf++) {
                unsigned b[2];
                uint32_t b_addr = b_base +
                    ((((ks * 16) + (lane & 15)) * SB + nf * 8) << 1);
                ldsm_x2_trans(b, b_addr);
                mma16816(acc[nf], a, b);
            }
        }
        __syncthreads();
    }

    // Epilogue: D-fragment mapping -> fp16 H
    const int tig = lane & 3;            // thread-in-group
    const int grp = lane >> 2;           // row group
    const int r0 = row0 + wm0 + grp;
    const int r1 = r0 + 8;
#pragma unroll
    for (int nf = 0; nf < 8; nf++) {
        int col = nf * 8 + tig * 2;
        if (r0 < M) {
            __half2 h = __floats2half2_rn(acc[nf][0], acc[nf][1]);
            *(__half2*)&Hout[(size_t)r0 * 64 + col] = h;
        }
        if (r1 < M) {
            __half2 h = __floats2half2_rn(acc[nf][2], acc[nf][3]);
            *(__half2*)&Hout[(size_t)r1 * 64 + col] = h;
        }
    }
}

// ---------------------------------------------------------------------------
// CSR gather (fp16 H, fp32 accumulate):
//   agg[n] = bias + dinv[n]*( dinv[n]*H[n] + sum_src dinv[src]*H[src] )
// 8 threads per node, each owns 8 channels (uint4 = 8 halves = 16 B).
// ---------------------------------------------------------------------------
template <bool LAYER2>
__global__ void gather_kernel(const float* __restrict__ bias,
                              float* __restrict__ AGGout, int M) {
    const __half* H   = LAYER2 ? g_H2h  : g_H1h;
    float*        agg = LAYER2 ? AGGout : g_agg1;
    const uint4*  Hv  = (const uint4*)H;   // 8 uint4 per node row

    long long gid = (long long)blockIdx.x * blockDim.x + threadIdx.x;
    int n = (int)(gid >> 3);
    if (n >= M) return;
    int lane = (int)(gid & 7);

    float dn = g_dinv[n];
    float a[8];
    {
        uint4 hv = Hv[(size_t)n * 8 + lane];     // self term
        const __half2* h2 = (const __half2*)&hv;
#pragma unroll
        for (int q = 0; q < 4; q++) {
            float2 f = __half22float2(h2[q]);
            a[2 * q + 0] = dn * f.x;
            a[2 * q + 1] = dn * f.y;
        }
    }

    int s = g_off[n], e = g_off[n + 1];
    for (int j = s; j < e; j++) {
        int r = g_srcs[j];                        // broadcast across 8 lanes
        float w = g_dinv[r];
        uint4 hv = Hv[(size_t)r * 8 + lane];
        const __half2* h2 = (const __half2*)&hv;
#pragma unroll
        for (int q = 0; q < 4; q++) {
            float2 f = __half22float2(h2[q]);
            a[2 * q + 0] += w * f.x;
            a[2 * q + 1] += w * f.y;
        }
    }

    size_t base = (size_t)n * 64 + lane * 8;
    float4 b0 = *(const float4*)&bias[lane * 8];
    float4 b1 = *(const float4*)&bias[lane * 8 + 4];
    float4 o0 = make_float4(b0.x + dn * a[0], b0.y + dn * a[1],
                            b0.z + dn * a[2], b0.w + dn * a[3]);
    float4 o1 = make_float4(b1.x + dn * a[4], b1.y + dn * a[5],
                            b1.z + dn * a[6], b1.w + dn * a[7]);
    *(float4*)&agg[base] = o0;
    *(float4*)&agg[base + 4] = o1;
}

// ---------------------------------------------------------------------------
extern "C" void kernel_launch(void* const* d_in, const int* in_sizes, int n_in,
                              void* d_out, int out_size) {
    const float* x  = (const float*)d_in[0];
    const void*  ei = d_in[1];
    const float* W1 = (const float*)d_in[2];
    const float* b1 = (const float*)d_in[3];
    const float* W2 = (const float*)d_in[4];
    const float* b2 = (const float*)d_in[5];
    float*       out = (float*)d_out;

    const int M = in_sizes[0] / 128;   // 100000
    const int E = in_sizes[1] / 2;     // 1600000
    const int NB = (M + 255) / 256;
    const int T = 256;

    // 1-3: dtype detect + counts + dinv/scanA
    init_kernel<<<(M + T - 1) / T, T>>>((const unsigned int*)ei, M, E);
    count_kernel<<<(E + T - 1) / T, T>>>(ei, E);
    scan_a_kernel<<<NB, 256>>>(M);
    // 4: layer-1 GEMM (tensor cores) — ncu capture slot
    gcn_gemm_kernel<128, false><<<(M + 127) / 128, T>>>(x, W1, M);
    // 5-7: CSR offsets + fill
    scan_b_kernel<<<1, 1024>>>(NB, M);
    scan_c_kernel<<<NB, 256>>>(M);
    fill_kernel<<<(E + T - 1) / T, T>>>(ei, E);
    // 8: layer-1 aggregate (fp32 out)
    gather_kernel<false><<<(int)(((long long)M * 8 + T - 1) / T), T>>>(b1, nullptr, M);
    // 9-10: layer 2 (gather writes d_out)
    gcn_gemm_kernel<64, true><<<(M + 127) / 128, T>>>(nullptr, W2, M);
    gather_kernel<true><<<(int)(((long long)M * 8 + T - 1) / T), T>>>(b2, out, M);
}

// round 14
// speedup vs baseline: 1.4946x; 1.0146x over previous
#include <cuda_runtime.h>
#include <cuda_fp16.h>
#include <cstdint>

#define MAXN 100000
#define MAXE 1700000
#define FDIM 64
#define NB_MAX ((MAXN + 255) / 256)   // 391

// Scratch — __device__ globals, referenced DIRECTLY in kernels.
__device__ int    g_is64;           // 1 if edge_index is int64, 0 if int32
__device__ int    g_cnt[MAXN];
__device__ int    g_off[MAXN + 1];
__device__ int    g_cursor[MAXN];
__device__ int    g_srcs[MAXE];
__device__ int    g_blockoff[NB_MAX];
__device__ float  g_dinv[MAXN];
__device__ __half g_H1h[(size_t)MAXN * FDIM];   // fp16 hidden, layer 1
__device__ __half g_agg1h[(size_t)MAXN * FDIM]; // fp16 layer-1 aggregate
__device__ __half g_H2h[(size_t)MAXN * FDIM];   // fp16 hidden, layer 2

// ---------------------------------------------------------------------------
// init: detect edge dtype (thread 0) + zero g_cnt.
// ---------------------------------------------------------------------------
__global__ void init_kernel(const unsigned int* __restrict__ raw, int M, int E) {
    int i = blockIdx.x * blockDim.x + threadIdx.x;
    if (i < M) g_cnt[i] = 0;
    if (i == 0) {
        int nz = 0;
        int lim = E < 64 ? E : 64;
        for (int k = 0; k < lim; k++)
            if (raw[2 * k + 1] != 0u) nz++;
        g_is64 = (nz == 0) ? 1 : 0;
    }
}

__device__ __forceinline__ int edge_at(const void* ei, int is64, size_t idx) {
    if (is64) return (int)((const long long*)ei)[idx];
    return ((const int*)ei)[idx];
}

__global__ void count_kernel(const void* __restrict__ ei, int E) {
    int e = blockIdx.x * blockDim.x + threadIdx.x;
    if (e < E) {
        int is64 = g_is64;
        int c = edge_at(ei, is64, (size_t)E + e);  // target node
        atomicAdd(&g_cnt[c], 1);
    }
}

// --- 3-phase grid-wide exclusive scan of g_cnt -> g_off (A also emits dinv) ---
__global__ void scan_a_kernel(int M) {
    __shared__ int sh[256];
    int tid = threadIdx.x;
    int i = blockIdx.x * 256 + tid;
    int v = (i < M) ? g_cnt[i] : 0;
    if (i < M) g_dinv[i] = rsqrtf((float)(v + 1));
    sh[tid] = v;
    __syncthreads();
#pragma unroll
    for (int d = 128; d > 0; d >>= 1) {
        if (tid < d) sh[tid] += sh[tid + d];
        __syncthreads();
    }
    if (tid == 0) g_blockoff[blockIdx.x] = sh[0];
}

__global__ void scan_b_kernel(int NB, int M) {
    __shared__ int sh[1024];
    int tid = threadIdx.x;
    int v = (tid < NB) ? g_blockoff[tid] : 0;
    sh[tid] = v;
    __syncthreads();
    for (int d = 1; d < 1024; d <<= 1) {
        int t = (tid >= d) ? sh[tid - d] : 0;
        __syncthreads();
        sh[tid] += t;
        __syncthreads();
    }
    if (tid < NB) g_blockoff[tid] = sh[tid] - v;   // exclusive
    if (tid == NB - 1) g_off[M] = sh[tid];
}

__global__ void scan_c_kernel(int M) {
    __shared__ int sh[256];
    int tid = threadIdx.x;
    int i = blockIdx.x * 256 + tid;
    int v = (i < M) ? g_cnt[i] : 0;
    sh[tid] = v;
    __syncthreads();
    for (int d = 1; d < 256; d <<= 1) {
        int t = (tid >= d) ? sh[tid - d] : 0;
        __syncthreads();
        sh[tid] += t;
        __syncthreads();
    }
    if (i < M) {
        int pos = g_blockoff[blockIdx.x] + sh[tid] - v;  // exclusive
        g_off[i] = pos;
        g_cursor[i] = pos;
    }
}

__global__ void fill_kernel(const void* __restrict__ ei, int E) {
    int e = blockIdx.x * blockDim.x + threadIdx.x;
    if (e < E) {
        int is64 = g_is64;
        int r = edge_at(ei, is64, (size_t)e);           // source
        int c = edge_at(ei, is64, (size_t)E + e);       // target
        int pos = atomicAdd(&g_cursor[c], 1);
        g_srcs[pos] = r;
    }
}

// ---------------------------------------------------------------------------
// Tensor-core GEMM (HMMA): H = fp16( act(X) @ W ), dinv applied in gather.
// Layer1: X fp32 -> convert in staging. Layer2: X already fp16 (agg1h), ReLU.
// 256 threads = 8 warps; CTA tile 128x64; warp tile 16x64.
// ---------------------------------------------------------------------------
__device__ __forceinline__ void ldsm_x4(unsigned* r, uint32_t addr) {
    asm volatile("ldmatrix.sync.aligned.m8n8.x4.shared.b16 {%0,%1,%2,%3}, [%4];"
                 : "=r"(r[0]), "=r"(r[1]), "=r"(r[2]), "=r"(r[3]) : "r"(addr));
}
__device__ __forceinline__ void ldsm_x2_trans(unsigned* r, uint32_t addr) {
    asm volatile("ldmatrix.sync.aligned.m8n8.x2.trans.shared.b16 {%0,%1}, [%2];"
                 : "=r"(r[0]), "=r"(r[1]) : "r"(addr));
}
__device__ __forceinline__ void mma16816(float* d, const unsigned* a,
                                         const unsigned* b) {
    asm volatile(
        "mma.sync.aligned.m16n8k16.row.col.f32.f16.f16.f32 "
        "{%0,%1,%2,%3}, {%4,%5,%6,%7}, {%8,%9}, {%0,%1,%2,%3};"
        : "+f"(d[0]), "+f"(d[1]), "+f"(d[2]), "+f"(d[3])
        : "r"(a[0]), "r"(a[1]), "r"(a[2]), "r"(a[3]), "r"(b[0]), "r"(b[1]));
}

template <int K, bool LAYER2>
__global__ void __launch_bounds__(256)
gcn_gemm_kernel(const float* __restrict__ Xin, const float* __restrict__ W,
                int M) {
    __half* Hout = LAYER2 ? g_H2h : g_H1h;

    constexpr int KT = 64;
    constexpr int SA = 72;               // A smem stride (halves); 144B rows
    constexpr int SB = 72;
    __shared__ __half As[128 * SA];
    __shared__ __half Bs[KT * SB];

    const int tid  = threadIdx.x;
    const int warp = tid >> 5;
    const int lane = tid & 31;
    const int row0 = blockIdx.x * 128;
    const int wm0  = warp * 16;

    float acc[8][4];
#pragma unroll
    for (int nf = 0; nf < 8; nf++)
#pragma unroll
        for (int q = 0; q < 4; q++) acc[nf][q] = 0.0f;

    const uint32_t a_base = (uint32_t)__cvta_generic_to_shared(&As[0]);
    const uint32_t b_base = (uint32_t)__cvta_generic_to_shared(&Bs[0]);

    for (int k0 = 0; k0 < K; k0 += KT) {
        if (LAYER2) {
            // Stage A from fp16 agg1h, ReLU in half2. 128 rows x 64 halves
            // = 1024 x uint4(16B); 4 iters x 256 threads.
            const __half2 z2 = __float2half2_rn(0.f);
#pragma unroll
            for (int t = 0; t < 4; t++) {
                int idx = tid + t * 256;
                int r = idx >> 3;            // row
                int j = idx & 7;             // uint4 group (8 halves)
                int row = row0 + r;
                uint4 hv = make_uint4(0u, 0u, 0u, 0u);
                if (row < M)
                    hv = *(const uint4*)&g_agg1h[(size_t)row * 64 + k0 + j * 8];
                __half2* h2 = (__half2*)&hv;
#pragma unroll
                for (int q = 0; q < 4; q++) h2[q] = __hmax2(h2[q], z2);
                *(uint4*)&As[r * SA + j * 8] = hv;
            }
        } else {
            // Stage A from fp32 X, convert. 128 rows x 64 k floats.
#pragma unroll
            for (int t = 0; t < 8; t++) {
                int idx = tid + t * 256;
                int r = idx >> 4;
                int j = idx & 15;
                int row = row0 + r;
                float4 v = make_float4(0.f, 0.f, 0.f, 0.f);
                if (row < M)
                    v = *(const float4*)&Xin[(size_t)row * K + k0 + j * 4];
                __half2 h0 = __floats2half2_rn(v.x, v.y);
                __half2 h1 = __floats2half2_rn(v.z, v.w);
                uint2 st;
                st.x = *(unsigned*)&h0;
                st.y = *(unsigned*)&h1;
                *(uint2*)&As[r * SA + j * 4] = st;
            }
        }
        // Stage B: 64 k-rows x 64 n, fp32->fp16, k-major
#pragma unroll
        for (int t = 0; t < 4; t++) {
            int idx = tid + t * 256;
            int r = idx >> 4;
            int j = idx & 15;
            float4 v = *(const float4*)&W[(size_t)(k0 + r) * 64 + j * 4];
            __half2 h0 = __floats2half2_rn(v.x, v.y);
            __half2 h1 = __floats2half2_rn(v.z, v.w);
            uint2 st;
            st.x = *(unsigned*)&h0;
            st.y = *(unsigned*)&h1;
            *(uint2*)&Bs[r * SB + j * 4] = st;
        }
        __syncthreads();

#pragma unroll
        for (int ks = 0; ks < KT / 16; ks++) {
            unsigned a[4];
            uint32_t a_addr = a_base +
                (((wm0 + (lane & 15)) * SA + ks * 16 + (lane >> 4) * 8) << 1);
            ldsm_x4(a, a_addr);
#pragma unroll
            for (int nf = 0; nf < 8; nf++) {
                unsigned b[2];
                uint32_t b_addr = b_base +
                    ((((ks * 16) + (lane & 15)) * SB + nf * 8) << 1);
                ldsm_x2_trans(b, b_addr);
                mma16816(acc[nf], a, b);
            }
        }
        __syncthreads();
    }

    // Epilogue: D-fragment mapping -> fp16 H
    const int tig = lane & 3;
    const int grp = lane >> 2;
    const int r0 = row0 + wm0 + grp;
    const int r1 = r0 + 8;
#pragma unroll
    for (int nf = 0; nf < 8; nf++) {
        int col = nf * 8 + tig * 2;
        if (r0 < M) {
            __half2 h = __floats2half2_rn(acc[nf][0], acc[nf][1]);
            *(__half2*)&Hout[(size_t)r0 * 64 + col] = h;
        }
        if (r1 < M) {
            __half2 h = __floats2half2_rn(acc[nf][2], acc[nf][3]);
            *(__half2*)&Hout[(size_t)r1 * 64 + col] = h;
        }
    }
}

// ---------------------------------------------------------------------------
// CSR gather (fp16 H, fp32 accumulate), 4x unrolled edge loop for MLP:
//   agg[n] = bias + dinv[n]*( dinv[n]*H[n] + sum_src dinv[src]*H[src] )
// 8 threads/node, each owns 8 channels (uint4 = 8 halves = 16 B).
// Layer1 writes fp16 agg1h; layer2 writes fp32 d_out.
// ---------------------------------------------------------------------------
__device__ __forceinline__ void acc8(float* a, uint4 hv, float w) {
    const __half2* h2 = (const __half2*)&hv;
#pragma unroll
    for (int q = 0; q < 4; q++) {
        float2 f = __half22float2(h2[q]);
        a[2 * q + 0] += w * f.x;
        a[2 * q + 1] += w * f.y;
    }
}

template <bool LAYER2>
__global__ void gather_kernel(const float* __restrict__ bias,
                              float* __restrict__ OUT, int M) {
    const uint4* Hv = (const uint4*)(LAYER2 ? g_H2h : g_H1h);

    long long gid = (long long)blockIdx.x * blockDim.x + threadIdx.x;
    int n = (int)(gid >> 3);
    if (n >= M) return;
    int lane = (int)(gid & 7);

    float dn = g_dinv[n];
    float a[8];
    {
        uint4 hv = Hv[(size_t)n * 8 + lane];     // self term
        const __half2* h2 = (const __half2*)&hv;
#pragma unroll
        for (int q = 0; q < 4; q++) {
            float2 f = __half22float2(h2[q]);
            a[2 * q + 0] = dn * f.x;
            a[2 * q + 1] = dn * f.y;
        }
    }

    int s = g_off[n], e = g_off[n + 1];
    int j = s;
    // 4x unroll: 4 independent LDG.128 in flight per lane
    for (; j + 3 < e; j += 4) {
        int r0 = g_srcs[j], r1 = g_srcs[j + 1];
        int r2 = g_srcs[j + 2], r3 = g_srcs[j + 3];
        float w0 = g_dinv[r0], w1 = g_dinv[r1];
        float w2 = g_dinv[r2], w3 = g_dinv[r3];
        uint4 h0 = Hv[(size_t)r0 * 8 + lane];
        uint4 h1 = Hv[(size_t)r1 * 8 + lane];
        uint4 h2 = Hv[(size_t)r2 * 8 + lane];
        uint4 h3 = Hv[(size_t)r3 * 8 + lane];
        acc8(a, h0, w0); acc8(a, h1, w1);
        acc8(a, h2, w2); acc8(a, h3, w3);
    }
    for (; j < e; j++) {
        int r = g_srcs[j];
        acc8(a, Hv[(size_t)r * 8 + lane], g_dinv[r]);
    }

    float4 b0 = *(const float4*)&bias[lane * 8];
    float4 b1 = *(const float4*)&bias[lane * 8 + 4];
    float o[8];
    o[0] = b0.x + dn * a[0]; o[1] = b0.y + dn * a[1];
    o[2] = b0.z + dn * a[2]; o[3] = b0.w + dn * a[3];
    o[4] = b1.x + dn * a[4]; o[5] = b1.y + dn * a[5];
    o[6] = b1.z + dn * a[6]; o[7] = b1.w + dn * a[7];

    if (LAYER2) {
        size_t base = (size_t)n * 64 + lane * 8;
        *(float4*)&OUT[base]     = make_float4(o[0], o[1], o[2], o[3]);
        *(float4*)&OUT[base + 4] = make_float4(o[4], o[5], o[6], o[7]);
    } else {
        // fp16 agg1 (ReLU applied later in gemm2 staging)
        uint4 st;
        __half2* h2 = (__half2*)&st;
        h2[0] = __floats2half2_rn(o[0], o[1]);
        h2[1] = __floats2half2_rn(o[2], o[3]);
        h2[2] = __floats2half2_rn(o[4], o[5]);
        h2[3] = __floats2half2_rn(o[6], o[7]);
        *(uint4*)&g_agg1h[(size_t)n * 64 + lane * 8] = st;
    }
}

// ---------------------------------------------------------------------------
extern "C" void kernel_launch(void* const* d_in, const int* in_sizes, int n_in,
                              void* d_out, int out_size) {
    const float* x  = (const float*)d_in[0];
    const void*  ei = d_in[1];
    const float* W1 = (const float*)d_in[2];
    const float* b1 = (const float*)d_in[3];
    const float* W2 = (const float*)d_in[4];
    const float* b2 = (const float*)d_in[5];
    float*       out = (float*)d_out;

    const int M = in_sizes[0] / 128;   // 100000
    const int E = in_sizes[1] / 2;     // 1600000
    const int NB = (M + 255) / 256;
    const int T = 256;

    // 1-3: dtype detect + counts + dinv/scanA
    init_kernel<<<(M + T - 1) / T, T>>>((const unsigned int*)ei, M, E);
    count_kernel<<<(E + T - 1) / T, T>>>(ei, E);
    scan_a_kernel<<<NB, 256>>>(M);
    // 4: layer-1 GEMM (tensor cores) — ncu capture slot
    gcn_gemm_kernel<128, false><<<(M + 127) / 128, T>>>(x, W1, M);
    // 5-7: CSR offsets + fill
    scan_b_kernel<<<1, 1024>>>(NB, M);
    scan_c_kernel<<<NB, 256>>>(M);
    fill_kernel<<<(E + T - 1) / T, T>>>(ei, E);
    // 8: layer-1 aggregate (fp16 out)
    gather_kernel<false><<<(int)(((long long)M * 8 + T - 1) / T), T>>>(b1, nullptr, M);
    // 9-10: layer 2 (gather writes d_out fp32)
    gcn_gemm_kernel<64, true><<<(M + 127) / 128, T>>>(nullptr, W2, M);
    gather_kernel<true><<<(int)(((long long)M * 8 + T - 1) / T), T>>>(b2, out, M);
}

// round 15
// speedup vs baseline: 1.5205x; 1.0174x over previous
#include <cuda_runtime.h>
#include <cuda_fp16.h>
#include <cstdint>

#define MAXN 100000
#define MAXE 1700000
#define FDIM 64
#define NB_MAX ((MAXN + 255) / 256)   // 391

// Scratch — __device__ globals, referenced DIRECTLY in kernels.
__device__ int    g_is64;           // 1 if edge_index is int64, 0 if int32
__device__ int    g_cnt[MAXN];
__device__ int    g_off[MAXN + 1];
__device__ int    g_cursor[MAXN];
__device__ int    g_srcs[MAXE];
__device__ int    g_blockoff[NB_MAX];
__device__ float  g_dinv[MAXN];
__device__ __half g_H1h[(size_t)MAXN * FDIM];   // fp16 hidden, layer 1
__device__ __half g_agg1h[(size_t)MAXN * FDIM]; // fp16 layer-1 aggregate
__device__ __half g_H2h[(size_t)MAXN * FDIM];   // fp16 hidden, layer 2

// ---------------------------------------------------------------------------
// init: detect edge dtype (thread 0) + zero g_cnt.
// ---------------------------------------------------------------------------
__global__ void init_kernel(const unsigned int* __restrict__ raw, int M, int E) {
    int i = blockIdx.x * blockDim.x + threadIdx.x;
    if (i < M) g_cnt[i] = 0;
    if (i == 0) {
        int nz = 0;
        int lim = E < 64 ? E : 64;
        for (int k = 0; k < lim; k++)
            if (raw[2 * k + 1] != 0u) nz++;
        g_is64 = (nz == 0) ? 1 : 0;
    }
}

// ---------------------------------------------------------------------------
// count: 4 edges per thread, vectorized loads.
// ---------------------------------------------------------------------------
__global__ void count_kernel(const void* __restrict__ ei, int E) {
    int t = blockIdx.x * blockDim.x + threadIdx.x;
    int e0 = t * 4;
    if (e0 >= E) return;
    int n = min(4, E - e0);
    int c[4];
    if (g_is64) {
        const long long* p = (const long long*)ei + E + e0;
        if (n == 4) {
            longlong2 a = *(const longlong2*)p;
            longlong2 b = *(const longlong2*)(p + 2);
            c[0] = (int)a.x; c[1] = (int)a.y; c[2] = (int)b.x; c[3] = (int)b.y;
        } else {
            for (int i = 0; i < n; i++) c[i] = (int)p[i];
        }
    } else {
        const int* p = (const int*)ei + E + e0;
        if (n == 4) {
            int4 a = *(const int4*)p;
            c[0] = a.x; c[1] = a.y; c[2] = a.z; c[3] = a.w;
        } else {
            for (int i = 0; i < n; i++) c[i] = p[i];
        }
    }
    for (int i = 0; i < n; i++) atomicAdd(&g_cnt[c[i]], 1);
}

// --- grid-wide exclusive scan of g_cnt -> g_off ---
__global__ void scan_a_kernel(int M) {
    __shared__ int sh[256];
    int tid = threadIdx.x;
    int i = blockIdx.x * 256 + tid;
    int v = (i < M) ? g_cnt[i] : 0;
    if (i < M) g_dinv[i] = rsqrtf((float)(v + 1));
    sh[tid] = v;
    __syncthreads();
#pragma unroll
    for (int d = 128; d > 0; d >>= 1) {
        if (tid < d) sh[tid] += sh[tid + d];
        __syncthreads();
    }
    if (tid == 0) g_blockoff[blockIdx.x] = sh[0];
}

// scan_b: 128 threads, warp-shuffle scan of NB block sums (no sync chains).
__global__ void scan_b_kernel(int NB, int M) {
    __shared__ int warp_tot[4];
    int tid = threadIdx.x;
    int lane = tid & 31, warp = tid >> 5;
    int nper = (NB + 127) / 128;           // <= 8 for NB <= 1024
    int start = tid * nper;
    int local[8];
    int s = 0;
    for (int i = 0; i < nper; i++) {
        int idx = start + i;
        int v = (idx < NB) ? g_blockoff[idx] : 0;
        local[i] = v; s += v;
    }
    int incl = s;
#pragma unroll
    for (int d = 1; d < 32; d <<= 1) {
        int t = __shfl_up_sync(0xffffffffu, incl, d);
        if (lane >= d) incl += t;
    }
    if (lane == 31) warp_tot[warp] = incl;
    __syncthreads();
    int woff = 0;
    for (int w = 0; w < warp; w++) woff += warp_tot[w];
    int run = woff + incl - s;             // exclusive prefix of this chunk
    for (int i = 0; i < nper; i++) {
        int idx = start + i;
        if (idx < NB) { g_blockoff[idx] = run; run += local[i]; }
    }
    if (tid == 127) g_off[M] = run;        // total (all chunks <= tid included)
}

__global__ void scan_c_kernel(int M) {
    __shared__ int sh[256];
    int tid = threadIdx.x;
    int i = blockIdx.x * 256 + tid;
    int v = (i < M) ? g_cnt[i] : 0;
    sh[tid] = v;
    __syncthreads();
    for (int d = 1; d < 256; d <<= 1) {
        int t = (tid >= d) ? sh[tid - d] : 0;
        __syncthreads();
        sh[tid] += t;
        __syncthreads();
    }
    if (i < M) {
        int pos = g_blockoff[blockIdx.x] + sh[tid] - v;  // exclusive
        g_off[i] = pos;
        g_cursor[i] = pos;
    }
}

// ---------------------------------------------------------------------------
// fill: 4 edges per thread, vectorized loads of rows and cols.
// ---------------------------------------------------------------------------
__global__ void fill_kernel(const void* __restrict__ ei, int E) {
    int t = blockIdx.x * blockDim.x + threadIdx.x;
    int e0 = t * 4;
    if (e0 >= E) return;
    int n = min(4, E - e0);
    int r[4], c[4];
    if (g_is64) {
        const long long* pr = (const long long*)ei + e0;
        const long long* pc = (const long long*)ei + E + e0;
        if (n == 4) {
            longlong2 a = *(const longlong2*)pr;
            longlong2 b = *(const longlong2*)(pr + 2);
            longlong2 x = *(const longlong2*)pc;
            longlong2 y = *(const longlong2*)(pc + 2);
            r[0] = (int)a.x; r[1] = (int)a.y; r[2] = (int)b.x; r[3] = (int)b.y;
            c[0] = (int)x.x; c[1] = (int)x.y; c[2] = (int)y.x; c[3] = (int)y.y;
        } else {
            for (int i = 0; i < n; i++) { r[i] = (int)pr[i]; c[i] = (int)pc[i]; }
        }
    } else {
        const int* pr = (const int*)ei + e0;
        const int* pc = (const int*)ei + E + e0;
        if (n == 4) {
            int4 a = *(const int4*)pr;
            int4 x = *(const int4*)pc;
            r[0] = a.x; r[1] = a.y; r[2] = a.z; r[3] = a.w;
            c[0] = x.x; c[1] = x.y; c[2] = x.z; c[3] = x.w;
        } else {
            for (int i = 0; i < n; i++) { r[i] = pr[i]; c[i] = pc[i]; }
        }
    }
    for (int i = 0; i < n; i++) {
        int pos = atomicAdd(&g_cursor[c[i]], 1);
        g_srcs[pos] = r[i];
    }
}

// ---------------------------------------------------------------------------
// Tensor-core GEMM (HMMA), full-K smem staging, XOR-swizzled (no padding):
//   A: 128 rows x K halves, row stride = K halves; 16B chunk c at row r is
//      stored at chunk (c ^ (r&7)) — conflict-free ldmatrix + staging.
//   B: K rows x 64 halves, same swizzle on k-row.
// One __syncthreads; all DRAM loads issue in one burst per CTA.
// ---------------------------------------------------------------------------
__device__ __forceinline__ void ldsm_x4(unsigned* r, uint32_t addr) {
    asm volatile("ldmatrix.sync.aligned.m8n8.x4.shared.b16 {%0,%1,%2,%3}, [%4];"
                 : "=r"(r[0]), "=r"(r[1]), "=r"(r[2]), "=r"(r[3]) : "r"(addr));
}
__device__ __forceinline__ void ldsm_x2_trans(unsigned* r, uint32_t addr) {
    asm volatile("ldmatrix.sync.aligned.m8n8.x2.trans.shared.b16 {%0,%1}, [%2];"
                 : "=r"(r[0]), "=r"(r[1]) : "r"(addr));
}
__device__ __forceinline__ void mma16816(float* d, const unsigned* a,
                                         const unsigned* b) {
    asm volatile(
        "mma.sync.aligned.m16n8k16.row.col.f32.f16.f16.f32 "
        "{%0,%1,%2,%3}, {%4,%5,%6,%7}, {%8,%9}, {%0,%1,%2,%3};"
        : "+f"(d[0]), "+f"(d[1]), "+f"(d[2]), "+f"(d[3])
        : "r"(a[0]), "r"(a[1]), "r"(a[2]), "r"(a[3]), "r"(b[0]), "r"(b[1]));
}

template <int K, bool LAYER2>
__global__ void __launch_bounds__(256)
gcn_gemm_kernel(const float* __restrict__ Xin, const float* __restrict__ W,
                int M) {
    __half* Hout = LAYER2 ? g_H2h : g_H1h;

    __shared__ __half As[128 * K];   // K=128: 32 KB ; K=64: 16 KB
    __shared__ __half Bs[K * 64];    // K=128: 16 KB ; K=64: 8 KB

    const int tid  = threadIdx.x;
    const int warp = tid >> 5;
    const int lane = tid & 31;
    const int row0 = blockIdx.x * 128;
    const int wm0  = warp * 16;

    float acc[8][4];
#pragma unroll
    for (int nf = 0; nf < 8; nf++)
#pragma unroll
        for (int q = 0; q < 4; q++) acc[nf][q] = 0.0f;

    const uint32_t a_base = (uint32_t)__cvta_generic_to_shared(&As[0]);
    const uint32_t b_base = (uint32_t)__cvta_generic_to_shared(&Bs[0]);

    constexpr int AC = K / 8;            // 16B chunks per A row
    // ---- Stage A (full K), one uint4 (8 halves) per iter ----
    if (LAYER2) {
        const __half2 z2 = __float2half2_rn(0.f);
#pragma unroll
        for (int t = 0; t < 128 * AC / 256; t++) {
            int idx = tid + t * 256;
            int r = idx / AC;
            int c16 = idx % AC;
            int row = row0 + r;
            uint4 hv = make_uint4(0u, 0u, 0u, 0u);
            if (row < M)
                hv = *(const uint4*)&g_agg1h[(size_t)row * 64 + c16 * 8];
            __half2* h2 = (__half2*)&hv;
#pragma unroll
            for (int q = 0; q < 4; q++) h2[q] = __hmax2(h2[q], z2);
            *(uint4*)&As[r * K + (c16 ^ (r & 7)) * 8] = hv;
        }
    } else {
#pragma unroll
        for (int t = 0; t < 128 * AC / 256; t++) {
            int idx = tid + t * 256;
            int r = idx / AC;
            int c16 = idx % AC;
            int row = row0 + r;
            float4 v0 = make_float4(0.f, 0.f, 0.f, 0.f);
            float4 v1 = make_float4(0.f, 0.f, 0.f, 0.f);
            if (row < M) {
                v0 = *(const float4*)&Xin[(size_t)row * K + c16 * 8];
                v1 = *(const float4*)&Xin[(size_t)row * K + c16 * 8 + 4];
            }
            uint4 st;
            __half2* h2 = (__half2*)&st;
            h2[0] = __floats2half2_rn(v0.x, v0.y);
            h2[1] = __floats2half2_rn(v0.z, v0.w);
            h2[2] = __floats2half2_rn(v1.x, v1.y);
            h2[3] = __floats2half2_rn(v1.z, v1.w);
            *(uint4*)&As[r * K + (c16 ^ (r & 7)) * 8] = st;
        }
    }
    // ---- Stage B (full K): K rows x 8 chunks ----
#pragma unroll
    for (int t = 0; t < K * 8 / 256; t++) {
        int idx = tid + t * 256;
        int kr = idx >> 3;
        int c16 = idx & 7;
        float4 v0 = *(const float4*)&W[(size_t)kr * 64 + c16 * 8];
        float4 v1 = *(const float4*)&W[(size_t)kr * 64 + c16 * 8 + 4];
        uint4 st;
        __half2* h2 = (__half2*)&st;
        h2[0] = __floats2half2_rn(v0.x, v0.y);
        h2[1] = __floats2half2_rn(v0.z, v0.w);
        h2[2] = __floats2half2_rn(v1.x, v1.y);
        h2[3] = __floats2half2_rn(v1.z, v1.w);
        *(uint4*)&Bs[kr * 64 + (c16 ^ (kr & 7)) * 8] = st;
    }
    __syncthreads();

    // ---- MMA over full K ----
#pragma unroll
    for (int ks = 0; ks < K / 16; ks++) {
        unsigned a[4];
        int arow = wm0 + (lane & 15);
        int ac16 = ks * 2 + (lane >> 4);
        uint32_t a_addr = a_base + ((arow * K + (ac16 ^ (arow & 7)) * 8) << 1);
        ldsm_x4(a, a_addr);
#pragma unroll
        for (int nf = 0; nf < 8; nf++) {
            unsigned b[2];
            int kr = ks * 16 + (lane & 15);
            uint32_t b_addr = b_base + ((kr * 64 + ((nf ^ (kr & 7)) * 8)) << 1);
            ldsm_x2_trans(b, b_addr);
            mma16816(acc[nf], a, b);
        }
    }

    // Epilogue: D-fragment mapping -> fp16 H
    const int tig = lane & 3;
    const int grp = lane >> 2;
    const int r0 = row0 + wm0 + grp;
    const int r1 = r0 + 8;
#pragma unroll
    for (int nf = 0; nf < 8; nf++) {
        int col = nf * 8 + tig * 2;
        if (r0 < M) {
            __half2 h = __floats2half2_rn(acc[nf][0], acc[nf][1]);
            *(__half2*)&Hout[(size_t)r0 * 64 + col] = h;
        }
        if (r1 < M) {
            __half2 h = __floats2half2_rn(acc[nf][2], acc[nf][3]);
            *(__half2*)&Hout[(size_t)r1 * 64 + col] = h;
        }
    }
}

// ---------------------------------------------------------------------------
// CSR gather (fp16 H, fp32 accumulate), 4x unrolled edge loop:
//   agg[n] = bias + dinv[n]*( dinv[n]*H[n] + sum_src dinv[src]*H[src] )
// 8 threads/node, each owns 8 channels (uint4 = 8 halves = 16 B).
// ---------------------------------------------------------------------------
__device__ __forceinline__ void acc8(float* a, uint4 hv, float w) {
    const __half2* h2 = (const __half2*)&hv;
#pragma unroll
    for (int q = 0; q < 4; q++) {
        float2 f = __half22float2(h2[q]);
        a[2 * q + 0] += w * f.x;
        a[2 * q + 1] += w * f.y;
    }
}

template <bool LAYER2>
__global__ void gather_kernel(const float* __restrict__ bias,
                              float* __restrict__ OUT, int M) {
    const uint4* Hv = (const uint4*)(LAYER2 ? g_H2h : g_H1h);

    long long gid = (long long)blockIdx.x * blockDim.x + threadIdx.x;
    int n = (int)(gid >> 3);
    if (n >= M) return;
    int lane = (int)(gid & 7);

    float dn = g_dinv[n];
    float a[8];
    {
        uint4 hv = Hv[(size_t)n * 8 + lane];     // self term
        const __half2* h2 = (const __half2*)&hv;
#pragma unroll
        for (int q = 0; q < 4; q++) {
            float2 f = __half22float2(h2[q]);
            a[2 * q + 0] = dn * f.x;
            a[2 * q + 1] = dn * f.y;
        }
    }

    int s = g_off[n], e = g_off[n + 1];
    int j = s;
    for (; j + 3 < e; j += 4) {
        int r0 = g_srcs[j], r1 = g_srcs[j + 1];
        int r2 = g_srcs[j + 2], r3 = g_srcs[j + 3];
        float w0 = g_dinv[r0], w1 = g_dinv[r1];
        float w2 = g_dinv[r2], w3 = g_dinv[r3];
        uint4 h0 = Hv[(size_t)r0 * 8 + lane];
        uint4 h1 = Hv[(size_t)r1 * 8 + lane];
        uint4 h2 = Hv[(size_t)r2 * 8 + lane];
        uint4 h3 = Hv[(size_t)r3 * 8 + lane];
        acc8(a, h0, w0); acc8(a, h1, w1);
        acc8(a, h2, w2); acc8(a, h3, w3);
    }
    for (; j < e; j++) {
        int r = g_srcs[j];
        acc8(a, Hv[(size_t)r * 8 + lane], g_dinv[r]);
    }

    float4 b0 = *(const float4*)&bias[lane * 8];
    float4 b1 = *(const float4*)&bias[lane * 8 + 4];
    float o[8];
    o[0] = b0.x + dn * a[0]; o[1] = b0.y + dn * a[1];
    o[2] = b0.z + dn * a[2]; o[3] = b0.w + dn * a[3];
    o[4] = b1.x + dn * a[4]; o[5] = b1.y + dn * a[5];
    o[6] = b1.z + dn * a[6]; o[7] = b1.w + dn * a[7];

    if (LAYER2) {
        size_t base = (size_t)n * 64 + lane * 8;
        *(float4*)&OUT[base]     = make_float4(o[0], o[1], o[2], o[3]);
        *(float4*)&OUT[base + 4] = make_float4(o[4], o[5], o[6], o[7]);
    } else {
        uint4 st;
        __half2* h2 = (__half2*)&st;
        h2[0] = __floats2half2_rn(o[0], o[1]);
        h2[1] = __floats2half2_rn(o[2], o[3]);
        h2[2] = __floats2half2_rn(o[4], o[5]);
        h2[3] = __floats2half2_rn(o[6], o[7]);
        *(uint4*)&g_agg1h[(size_t)n * 64 + lane * 8] = st;
    }
}

// ---------------------------------------------------------------------------
extern "C" void kernel_launch(void* const* d_in, const int* in_sizes, int n_in,
                              void* d_out, int out_size) {
    const float* x  = (const float*)d_in[0];
    const void*  ei = d_in[1];
    const float* W1 = (const float*)d_in[2];
    const float* b1 = (const float*)d_in[3];
    const float* W2 = (const float*)d_in[4];
    const float* b2 = (const float*)d_in[5];
    float*       out = (float*)d_out;

    const int M = in_sizes[0] / 128;   // 100000
    const int E = in_sizes[1] / 2;     // 1600000
    const int NB = (M + 255) / 256;
    const int T = 256;
    const int E4 = (E + 3) / 4;        // 4 edges per thread

    // 1-3: dtype detect + counts + dinv/scanA
    init_kernel<<<(M + T - 1) / T, T>>>((const unsigned int*)ei, M, E);
    count_kernel<<<(E4 + T - 1) / T, T>>>(ei, E);
    scan_a_kernel<<<NB, 256>>>(M);
    // 4: layer-1 GEMM (tensor cores) — ncu capture slot
    gcn_gemm_kernel<128, false><<<(M + 127) / 128, T>>>(x, W1, M);
    // 5-7: CSR offsets + fill
    scan_b_kernel<<<1, 128>>>(NB, M);
    scan_c_kernel<<<NB, 256>>>(M);
    fill_kernel<<<(E4 + T - 1) / T, T>>>(ei, E);
    // 8: layer-1 aggregate (fp16 out)
    gather_kernel<false><<<(int)(((long long)M * 8 + T - 1) / T), T>>>(b1, nullptr, M);
    // 9-10: layer 2 (gather writes d_out fp32)
    gcn_gemm_kernel<64, true><<<(M + 127) / 128, T>>>(nullptr, W2, M);
    gather_kernel<true><<<(int)(((long long)M * 8 + T - 1) / T), T>>>(b2, out, M);
}